// round 4
// baseline (speedup 1.0000x reference)
#include <cuda_runtime.h>
#include <math.h>

// Problem constants (fixed by reference: B=4, S=2048, D_MODEL=1024, H=16, DK=64)
#define BATCH    4
#define SEQ      2048
#define DMODEL   1024
#define NHEADS   16
#define DK       64
#define BHTOT    (BATCH * NHEADS)
#define MROWS    (BATCH * SEQ)          // 8192

// ---------------------------------------------------------------------------
// Scratch (static device globals — no runtime allocation)
// ---------------------------------------------------------------------------
__device__ float g_q[BHTOT * SEQ * DK];      // [b*H+h][s][d]
__device__ float g_k[BHTOT * SEQ * DK];
__device__ float g_v[BHTOT * SEQ * DK];
__device__ float g_ctx[MROWS * DMODEL];      // [b*S+s][h*DK+d]

// ---------------------------------------------------------------------------
// GEMM: C[m,n] = sum_k A[m,k] * W[n,k] + bias[n]   (NT, both K-contiguous)
// Tile 128x128x16, 256 threads, 8x8 micro-tile per thread.
// headsplit=1 writes to [b*H+h][s][d] layout for attention consumption.
// ---------------------------------------------------------------------------
#define GBM 128
#define GBN 128
#define GBK 16
#define GSTR 132   // padded smem stride (132*4B = 528B, 16B aligned per row)

__global__ __launch_bounds__(256) void gemm_nt_bias(
    const float* __restrict__ A, const float* __restrict__ W,
    const float* __restrict__ bias, float* __restrict__ C,
    int K, int N, int headsplit)
{
    __shared__ float As[GBK * GSTR];
    __shared__ float Bs[GBK * GSTR];

    const int tid = threadIdx.x;
    const int tx = tid & 15;          // 0..15 -> col group
    const int ty = tid >> 4;          // 0..15 -> row group
    const int mBase = blockIdx.y * GBM;
    const int nBase = blockIdx.x * GBN;

    const float* Aptr = A + (size_t)mBase * K;
    const float* Wptr = W + (size_t)nBase * K;

    float acc[8][8];
#pragma unroll
    for (int i = 0; i < 8; i++)
#pragma unroll
        for (int j = 0; j < 8; j++) acc[i][j] = 0.0f;

    for (int k0 = 0; k0 < K; k0 += GBK) {
        // Load 128x16 A tile and 128x16 W tile, transposed into smem [k][row]
#pragma unroll
        for (int i = 0; i < 2; i++) {
            int v   = tid * 2 + i;          // 0..511 float4 slots
            int row = v >> 2;               // 0..127
            int kc  = (v & 3) * 4;          // 0,4,8,12
            float4 a = *(const float4*)(Aptr + (size_t)row * K + k0 + kc);
            float4 b = *(const float4*)(Wptr + (size_t)row * K + k0 + kc);
            As[(kc + 0) * GSTR + row] = a.x;
            As[(kc + 1) * GSTR + row] = a.y;
            As[(kc + 2) * GSTR + row] = a.z;
            As[(kc + 3) * GSTR + row] = a.w;
            Bs[(kc + 0) * GSTR + row] = b.x;
            Bs[(kc + 1) * GSTR + row] = b.y;
            Bs[(kc + 2) * GSTR + row] = b.z;
            Bs[(kc + 3) * GSTR + row] = b.w;
        }
        __syncthreads();

#pragma unroll
        for (int k = 0; k < GBK; k++) {
            float a_frag[8], b_frag[8];
            *(float4*)(a_frag)     = *(const float4*)&As[k * GSTR + ty * 8];
            *(float4*)(a_frag + 4) = *(const float4*)&As[k * GSTR + ty * 8 + 4];
            *(float4*)(b_frag)     = *(const float4*)&Bs[k * GSTR + tx * 8];
            *(float4*)(b_frag + 4) = *(const float4*)&Bs[k * GSTR + tx * 8 + 4];
#pragma unroll
            for (int i = 0; i < 8; i++)
#pragma unroll
                for (int j = 0; j < 8; j++)
                    acc[i][j] = fmaf(a_frag[i], b_frag[j], acc[i][j]);
        }
        __syncthreads();
    }

    // Epilogue: bias add + store
#pragma unroll
    for (int i = 0; i < 8; i++) {
        int m = mBase + ty * 8 + i;
#pragma unroll
        for (int j = 0; j < 8; j++) {
            int n = nBase + tx * 8 + j;
            float v = acc[i][j] + bias[n];
            if (!headsplit) {
                C[(size_t)m * N + n] = v;
            } else {
                int b = m >> 11;          // /SEQ
                int s = m & (SEQ - 1);
                int h = n >> 6;           // /DK
                int d = n & (DK - 1);
                C[(((size_t)(b * NHEADS + h)) * SEQ + s) * DK + d] = v;
            }
        }
    }
}

// ---------------------------------------------------------------------------
// Flash attention: per (b,h), 64-row Q tiles, 64-col KV tiles, online softmax.
// 256 threads as 16x16, each owning a 4x4 sub-tile.
// smem: Qst [d][m] (stride 64), Kst [d][n] (stride 65, reused as P [m][n]
// stride 64 after S is consumed), Vs [n][d] (stride 64). Dynamic smem ~49.4KB.
// ---------------------------------------------------------------------------
#define FBM 64
#define FBN 64
#define KST 65
#define FLASH_SMEM ((FBM * DK + DK * KST + FBN * DK) * (int)sizeof(float))

extern __shared__ float fsm[];

__global__ __launch_bounds__(256) void flash_attn_kernel(
    const float* __restrict__ Q, const float* __restrict__ K,
    const float* __restrict__ V, float* __restrict__ Octx)
{
    float* Qst = fsm;                  // [64][64]  Qst[d*64 + m]
    float* Kst = fsm + FBM * DK;       // [64][65]  Kst[d*65 + n] ; P reuses this
    float* Vs  = Kst + DK * KST;       // [64][64]  Vs[n*64 + d]

    const int tid = threadIdx.x;
    const int tx = tid & 15;
    const int ty = tid >> 4;
    const int bh = blockIdx.y;
    const int mBase = blockIdx.x * FBM;

    const float* Qp = Q + (size_t)bh * SEQ * DK + (size_t)mBase * DK;
    const float* Kp = K + (size_t)bh * SEQ * DK;
    const float* Vp = V + (size_t)bh * SEQ * DK;

    // Load Q tile transposed (once per block)
    for (int idx = tid; idx < FBM * DK; idx += 256) {
        int m = idx >> 6, d = idx & 63;
        Qst[d * 64 + m] = Qp[idx];
    }

    float acc[4][4];
    float mi[4], li[4];
#pragma unroll
    for (int i = 0; i < 4; i++) {
        mi[i] = -1e30f;
        li[i] = 0.0f;
#pragma unroll
        for (int j = 0; j < 4; j++) acc[i][j] = 0.0f;
    }

    for (int n0 = 0; n0 < SEQ; n0 += FBN) {
        __syncthreads();   // prior iter's P/V reads done before overwrite
        for (int idx = tid; idx < FBN * DK; idx += 256) {
            int n = idx >> 6, d = idx & 63;
            Kst[d * KST + n] = Kp[(size_t)(n0 + n) * DK + d];
            Vs[idx]          = Vp[(size_t)n0 * DK + idx];
        }
        __syncthreads();

        // S = (Q K^T) * 1/sqrt(DK)
        float s[4][4];
#pragma unroll
        for (int i = 0; i < 4; i++)
#pragma unroll
            for (int j = 0; j < 4; j++) s[i][j] = 0.0f;

#pragma unroll 4
        for (int d = 0; d < DK; d++) {
            float4 a4 = *(const float4*)&Qst[d * 64 + ty * 4];
            float a[4] = {a4.x, a4.y, a4.z, a4.w};
            float b[4];
#pragma unroll
            for (int j = 0; j < 4; j++) b[j] = Kst[d * KST + tx * 4 + j];
#pragma unroll
            for (int i = 0; i < 4; i++)
#pragma unroll
                for (int j = 0; j < 4; j++)
                    s[i][j] = fmaf(a[i], b[j], s[i][j]);
        }
#pragma unroll
        for (int i = 0; i < 4; i++)
#pragma unroll
            for (int j = 0; j < 4; j++) s[i][j] *= 0.125f;

        // Online softmax (row reduction across the 16 tx lanes of the warp)
#pragma unroll
        for (int i = 0; i < 4; i++) {
            float rm = fmaxf(fmaxf(s[i][0], s[i][1]), fmaxf(s[i][2], s[i][3]));
#pragma unroll
            for (int off = 8; off > 0; off >>= 1)
                rm = fmaxf(rm, __shfl_xor_sync(0xffffffffu, rm, off));
            float mnew = fmaxf(mi[i], rm);
            float alpha = __expf(mi[i] - mnew);
            float rs = 0.0f;
#pragma unroll
            for (int j = 0; j < 4; j++) {
                s[i][j] = __expf(s[i][j] - mnew);
                rs += s[i][j];
            }
#pragma unroll
            for (int off = 8; off > 0; off >>= 1)
                rs += __shfl_xor_sync(0xffffffffu, rs, off);
            li[i] = li[i] * alpha + rs;
            mi[i] = mnew;
#pragma unroll
            for (int j = 0; j < 4; j++) acc[i][j] *= alpha;
        }

        __syncthreads();   // everyone done reading Kst before P overwrites it
        float* Ps = Kst;   // reuse K smem as P [m][n], stride 64
#pragma unroll
        for (int i = 0; i < 4; i++)
            *(float4*)&Ps[(ty * 4 + i) * 64 + tx * 4] =
                make_float4(s[i][0], s[i][1], s[i][2], s[i][3]);
        __syncthreads();

        // O += P @ V
#pragma unroll 4
        for (int n = 0; n < FBN; n++) {
            float4 v4 = *(const float4*)&Vs[n * 64 + tx * 4];
#pragma unroll
            for (int i = 0; i < 4; i++) {
                float p = Ps[(ty * 4 + i) * 64 + n];
                acc[i][0] = fmaf(p, v4.x, acc[i][0]);
                acc[i][1] = fmaf(p, v4.y, acc[i][1]);
                acc[i][2] = fmaf(p, v4.z, acc[i][2]);
                acc[i][3] = fmaf(p, v4.w, acc[i][3]);
            }
        }
    }

    // Epilogue: normalize, write back merged-head layout [b][s][h*DK+d]
    const int b = bh >> 4;
    const int h = bh & 15;
#pragma unroll
    for (int i = 0; i < 4; i++) {
        int srow = mBase + ty * 4 + i;
        float inv = 1.0f / li[i];
        float* dst = Octx + ((size_t)(b * SEQ + srow)) * DMODEL + h * DK + tx * 4;
        float4 o = make_float4(acc[i][0] * inv, acc[i][1] * inv,
                               acc[i][2] * inv, acc[i][3] * inv);
        *(float4*)dst = o;
    }
}

// ---------------------------------------------------------------------------
// Launch
// ---------------------------------------------------------------------------
extern "C" void kernel_launch(void* const* d_in, const int* in_sizes, int n_in,
                              void* d_out, int out_size)
{
    const float* query = (const float*)d_in[0];
    const float* key   = (const float*)d_in[1];
    const float* value = (const float*)d_in[2];
    const float* Wq    = (const float*)d_in[3];
    const float* bq    = (const float*)d_in[4];
    const float* Wk    = (const float*)d_in[5];
    const float* bk    = (const float*)d_in[6];
    const float* Wv    = (const float*)d_in[7];
    const float* bv    = (const float*)d_in[8];
    const float* Wo    = (const float*)d_in[9];
    const float* bo    = (const float*)d_in[10];
    float* out = (float*)d_out;

    float *qp, *kp, *vp, *ctxp;
    cudaGetSymbolAddress((void**)&qp,   g_q);
    cudaGetSymbolAddress((void**)&kp,   g_k);
    cudaGetSymbolAddress((void**)&vp,   g_v);
    cudaGetSymbolAddress((void**)&ctxp, g_ctx);

    cudaFuncSetAttribute(flash_attn_kernel,
                         cudaFuncAttributeMaxDynamicSharedMemorySize, FLASH_SMEM);

    dim3 gBlk(256);
    dim3 gGrid(DMODEL / GBN, MROWS / GBM);   // 8 x 64

    // Projections (head-split epilogue)
    gemm_nt_bias<<<gGrid, gBlk>>>(query, Wq, bq, qp, DMODEL, DMODEL, 1);
    gemm_nt_bias<<<gGrid, gBlk>>>(key,   Wk, bk, kp, DMODEL, DMODEL, 1);
    gemm_nt_bias<<<gGrid, gBlk>>>(value, Wv, bv, vp, DMODEL, DMODEL, 1);

    // Attention
    dim3 fGrid(SEQ / FBM, BHTOT);            // 32 x 64
    flash_attn_kernel<<<fGrid, 256, FLASH_SMEM>>>(qp, kp, vp, ctxp);

    // Output projection
    gemm_nt_bias<<<gGrid, gBlk>>>(ctxp, Wo, bo, out, DMODEL, DMODEL, 0);
}

// round 10
// speedup vs baseline: 1.1198x; 1.1198x over previous
#include <cuda_runtime.h>
#include <math.h>

// Problem constants (fixed by reference: B=4, S=2048, D_MODEL=1024, H=16, DK=64)
#define BATCH    4
#define SEQ      2048
#define DMODEL   1024
#define NHEADS   16
#define DK       64
#define BHTOT    (BATCH * NHEADS)
#define MROWS    (BATCH * SEQ)          // 8192

typedef unsigned long long u64;

// ---------------------------------------------------------------------------
// Packed fp32x2 helpers (Blackwell sm_100+ : SASS FFMA2 — 2x fp32 FMA/instr,
// bit-exact fp32 arithmetic; ptxas never auto-fuses, must come from PTX)
// ---------------------------------------------------------------------------
__device__ __forceinline__ u64 dup_f2(float x) {
    u64 r; asm("mov.b64 %0, {%1, %1};" : "=l"(r) : "f"(x)); return r;
}
__device__ __forceinline__ void fma_f2(u64& d, u64 a, u64 b) {
    asm("fma.rn.f32x2 %0, %1, %2, %0;" : "+l"(d) : "l"(a), "l"(b));
}
__device__ __forceinline__ void mul_f2(u64& d, u64 a, u64 b) {
    asm("mul.rn.f32x2 %0, %1, %2;" : "=l"(d) : "l"(a), "l"(b));
}
__device__ __forceinline__ float2 unp_f2(u64 v) {
    float lo, hi; asm("mov.b64 {%0, %1}, %2;" : "=f"(lo), "=f"(hi) : "l"(v));
    return make_float2(lo, hi);
}

// ---------------------------------------------------------------------------
// Scratch (static device globals — no runtime allocation)
// ---------------------------------------------------------------------------
__device__ float g_q[BHTOT * SEQ * DK];      // [b*H+h][s][d]
__device__ float g_k[BHTOT * SEQ * DK];
__device__ float g_v[BHTOT * SEQ * DK];
__device__ float g_ctx[MROWS * DMODEL];      // [b*S+s][h*DK+d]

// ---------------------------------------------------------------------------
// GEMM: C[m,n] = sum_k A[m,k] * W[n,k] + bias[n]   (NT, both K-contiguous)
// Tile 128x128x16, 256 threads, 8x8 micro-tile per thread.
// Accumulators packed as f32x2 pairs along n.
// ---------------------------------------------------------------------------
#define GBM 128
#define GBN 128
#define GBK 16
#define GSTR 132   // padded smem stride (132*4B = 528B, 16B aligned per row)

__global__ __launch_bounds__(256) void gemm_nt_bias(
    const float* __restrict__ A, const float* __restrict__ W,
    const float* __restrict__ bias, float* __restrict__ C,
    int K, int N, int headsplit)
{
    __shared__ float As[GBK * GSTR];
    __shared__ float Bs[GBK * GSTR];

    const int tid = threadIdx.x;
    const int tx = tid & 15;          // col group (8 cols = 4 pairs)
    const int ty = tid >> 4;          // row group (8 rows)
    const int mBase = blockIdx.y * GBM;
    const int nBase = blockIdx.x * GBN;

    const float* Aptr = A + (size_t)mBase * K;
    const float* Wptr = W + (size_t)nBase * K;

    u64 acc[8][4];                    // 8 rows x 4 col-pairs (packed)
#pragma unroll
    for (int i = 0; i < 8; i++)
#pragma unroll
        for (int j = 0; j < 4; j++) acc[i][j] = 0ull;   // == {0.0f, 0.0f}

    for (int k0 = 0; k0 < K; k0 += GBK) {
        // Load 128x16 A tile and 128x16 W tile, transposed into smem [k][row]
#pragma unroll
        for (int i = 0; i < 2; i++) {
            int v   = tid * 2 + i;          // 0..511 float4 slots
            int row = v >> 2;               // 0..127
            int kc  = (v & 3) * 4;          // 0,4,8,12
            float4 a = *(const float4*)(Aptr + (size_t)row * K + k0 + kc);
            float4 b = *(const float4*)(Wptr + (size_t)row * K + k0 + kc);
            As[(kc + 0) * GSTR + row] = a.x;
            As[(kc + 1) * GSTR + row] = a.y;
            As[(kc + 2) * GSTR + row] = a.z;
            As[(kc + 3) * GSTR + row] = a.w;
            Bs[(kc + 0) * GSTR + row] = b.x;
            Bs[(kc + 1) * GSTR + row] = b.y;
            Bs[(kc + 2) * GSTR + row] = b.z;
            Bs[(kc + 3) * GSTR + row] = b.w;
        }
        __syncthreads();

#pragma unroll
        for (int k = 0; k < GBK; k++) {
            float4 a0 = *(const float4*)&As[k * GSTR + ty * 8];
            float4 a1 = *(const float4*)&As[k * GSTR + ty * 8 + 4];
            ulonglong2 b0 = *(const ulonglong2*)&Bs[k * GSTR + tx * 8];
            ulonglong2 b1 = *(const ulonglong2*)&Bs[k * GSTR + tx * 8 + 4];
            u64 bb0 = b0.x, bb1 = b0.y, bb2 = b1.x, bb3 = b1.y;
            float av[8] = {a0.x, a0.y, a0.z, a0.w, a1.x, a1.y, a1.z, a1.w};
#pragma unroll
            for (int i = 0; i < 8; i++) {
                u64 ad = dup_f2(av[i]);
                fma_f2(acc[i][0], ad, bb0);
                fma_f2(acc[i][1], ad, bb1);
                fma_f2(acc[i][2], ad, bb2);
                fma_f2(acc[i][3], ad, bb3);
            }
        }
        __syncthreads();
    }

    // Epilogue: bias add + store (pairs never cross a 64-col head boundary)
#pragma unroll
    for (int i = 0; i < 8; i++) {
        int m = mBase + ty * 8 + i;
#pragma unroll
        for (int jp = 0; jp < 4; jp++) {
            int n = nBase + tx * 8 + jp * 2;
            float2 v = unp_f2(acc[i][jp]);
            v.x += bias[n];
            v.y += bias[n + 1];
            if (!headsplit) {
                *(float2*)&C[(size_t)m * N + n] = v;
            } else {
                int b = m >> 11;          // /SEQ
                int s = m & (SEQ - 1);
                int h = n >> 6;           // /DK
                int d = n & (DK - 1);
                *(float2*)&C[(((size_t)(b * NHEADS + h)) * SEQ + s) * DK + d] = v;
            }
        }
    }
}

// ---------------------------------------------------------------------------
// Flash attention: per (b,h), 64-row Q tiles, 64-col KV tiles, online softmax.
// 256 threads as 16x16, each owning a 4x4 sub-tile (2 packed col-pairs).
// Scale 1/sqrt(DK)=0.125 folded into the Q smem load (power of two: exact).
// smem: Qst [d][m] stride 64, Kst [d][n] stride 68 (float4-loadable, reused
// as P [m][n] stride 64 after S consumed), Vs [n][d] stride 64.
// P@V loop walks n in chunks of 4 so P rows load as one LDS.128 each
// (broadcast over tx lanes) — cuts crossbar traffic ~2.5x in that loop.
// ---------------------------------------------------------------------------
#define FBM 64
#define FBN 64
#define KST 68
#define FLASH_SMEM ((FBM * DK + DK * KST + FBN * DK) * (int)sizeof(float))

extern __shared__ float fsm[];

__global__ __launch_bounds__(256) void flash_attn_kernel(
    const float* __restrict__ Q, const float* __restrict__ K,
    const float* __restrict__ V, float* __restrict__ Octx)
{
    float* Qst = fsm;                  // [64][64]  Qst[d*64 + m]  (pre-scaled)
    float* Kst = fsm + FBM * DK;       // [64][68]  Kst[d*68 + n] ; P reuses this
    float* Vs  = Kst + DK * KST;       // [64][64]  Vs[n*64 + d]

    const int tid = threadIdx.x;
    const int tx = tid & 15;
    const int ty = tid >> 4;
    const int bh = blockIdx.y;
    const int mBase = blockIdx.x * FBM;

    const float* Qp = Q + (size_t)bh * SEQ * DK + (size_t)mBase * DK;
    const float* Kp = K + (size_t)bh * SEQ * DK;
    const float* Vp = V + (size_t)bh * SEQ * DK;

    // Load Q tile transposed (once per block), fold 1/sqrt(DK)
    for (int idx = tid; idx < FBM * DK; idx += 256) {
        int m = idx >> 6, d = idx & 63;
        Qst[d * 64 + m] = Qp[idx] * 0.125f;
    }

    u64 acc[4][2];                     // 4 rows x 2 col-pairs (packed)
    float mi[4], li[4];
#pragma unroll
    for (int i = 0; i < 4; i++) {
        mi[i] = -1e30f;
        li[i] = 0.0f;
        acc[i][0] = 0ull;
        acc[i][1] = 0ull;
    }

    for (int n0 = 0; n0 < SEQ; n0 += FBN) {
        __syncthreads();   // prior iter's P/V reads done before overwrite
        for (int idx = tid; idx < FBN * DK; idx += 256) {
            int n = idx >> 6, d = idx & 63;
            Kst[d * KST + n] = Kp[(size_t)(n0 + n) * DK + d];
            Vs[idx]          = Vp[(size_t)n0 * DK + idx];
        }
        __syncthreads();

        // S = Q K^T (scale pre-folded into Q)
        u64 sp[4][2];
#pragma unroll
        for (int i = 0; i < 4; i++) { sp[i][0] = 0ull; sp[i][1] = 0ull; }

#pragma unroll 4
        for (int d = 0; d < DK; d++) {
            float4 a4 = *(const float4*)&Qst[d * 64 + ty * 4];
            ulonglong2 b2 = *(const ulonglong2*)&Kst[d * KST + tx * 4];
            u64 ad0 = dup_f2(a4.x), ad1 = dup_f2(a4.y);
            u64 ad2 = dup_f2(a4.z), ad3 = dup_f2(a4.w);
            fma_f2(sp[0][0], ad0, b2.x); fma_f2(sp[0][1], ad0, b2.y);
            fma_f2(sp[1][0], ad1, b2.x); fma_f2(sp[1][1], ad1, b2.y);
            fma_f2(sp[2][0], ad2, b2.x); fma_f2(sp[2][1], ad2, b2.y);
            fma_f2(sp[3][0], ad3, b2.x); fma_f2(sp[3][1], ad3, b2.y);
        }

        // Unpack S
        float s[4][4];
#pragma unroll
        for (int i = 0; i < 4; i++) {
            float2 p0 = unp_f2(sp[i][0]);
            float2 p1 = unp_f2(sp[i][1]);
            s[i][0] = p0.x; s[i][1] = p0.y; s[i][2] = p1.x; s[i][3] = p1.y;
        }

        // Online softmax (row reduction across the 16 tx lanes of the warp)
#pragma unroll
        for (int i = 0; i < 4; i++) {
            float rm = fmaxf(fmaxf(s[i][0], s[i][1]), fmaxf(s[i][2], s[i][3]));
#pragma unroll
            for (int off = 8; off > 0; off >>= 1)
                rm = fmaxf(rm, __shfl_xor_sync(0xffffffffu, rm, off));
            float mnew = fmaxf(mi[i], rm);
            float alpha = __expf(mi[i] - mnew);
            float rs = 0.0f;
#pragma unroll
            for (int j = 0; j < 4; j++) {
                s[i][j] = __expf(s[i][j] - mnew);
                rs += s[i][j];
            }
#pragma unroll
            for (int off = 8; off > 0; off >>= 1)
                rs += __shfl_xor_sync(0xffffffffu, rs, off);
            li[i] = li[i] * alpha + rs;
            mi[i] = mnew;
            u64 al = dup_f2(alpha);
            mul_f2(acc[i][0], acc[i][0], al);
            mul_f2(acc[i][1], acc[i][1], al);
        }

        __syncthreads();   // everyone done reading Kst before P overwrites it
        float* Ps = Kst;   // reuse K smem as P [m][n], stride 64
#pragma unroll
        for (int i = 0; i < 4; i++)
            *(float4*)&Ps[(ty * 4 + i) * 64 + tx * 4] =
                make_float4(s[i][0], s[i][1], s[i][2], s[i][3]);
        __syncthreads();

        // O += P @ V  — n in chunks of 4; P rows as vector loads (broadcast)
#pragma unroll 2
        for (int n = 0; n < FBN; n += 4) {
            float4 p4[4];
#pragma unroll
            for (int i = 0; i < 4; i++)
                p4[i] = *(const float4*)&Ps[(ty * 4 + i) * 64 + n];
#pragma unroll
            for (int nn = 0; nn < 4; nn++) {
                ulonglong2 v2 = *(const ulonglong2*)&Vs[(n + nn) * 64 + tx * 4];
#pragma unroll
                for (int i = 0; i < 4; i++) {
                    u64 pd = dup_f2(((const float*)&p4[i])[nn]);
                    fma_f2(acc[i][0], pd, v2.x);
                    fma_f2(acc[i][1], pd, v2.y);
                }
            }
        }
    }

    // Epilogue: normalize, write back merged-head layout [b][s][h*DK+d]
    const int b = bh >> 4;
    const int h = bh & 15;
#pragma unroll
    for (int i = 0; i < 4; i++) {
        int srow = mBase + ty * 4 + i;
        float inv = 1.0f / li[i];
        float2 o0 = unp_f2(acc[i][0]);
        float2 o1 = unp_f2(acc[i][1]);
        float* dst = Octx + ((size_t)(b * SEQ + srow)) * DMODEL + h * DK + tx * 4;
        *(float4*)dst = make_float4(o0.x * inv, o0.y * inv, o1.x * inv, o1.y * inv);
    }
}

// ---------------------------------------------------------------------------
// Launch
// ---------------------------------------------------------------------------
extern "C" void kernel_launch(void* const* d_in, const int* in_sizes, int n_in,
                              void* d_out, int out_size)
{
    const float* query = (const float*)d_in[0];
    const float* key   = (const float*)d_in[1];
    const float* value = (const float*)d_in[2];
    const float* Wq    = (const float*)d_in[3];
    const float* bq    = (const float*)d_in[4];
    const float* Wk    = (const float*)d_in[5];
    const float* bk    = (const float*)d_in[6];
    const float* Wv    = (const float*)d_in[7];
    const float* bv    = (const float*)d_in[8];
    const float* Wo    = (const float*)d_in[9];
    const float* bo    = (const float*)d_in[10];
    float* out = (float*)d_out;

    float *qp, *kp, *vp, *ctxp;
    cudaGetSymbolAddress((void**)&qp,   g_q);
    cudaGetSymbolAddress((void**)&kp,   g_k);
    cudaGetSymbolAddress((void**)&vp,   g_v);
    cudaGetSymbolAddress((void**)&ctxp, g_ctx);

    cudaFuncSetAttribute(flash_attn_kernel,
                         cudaFuncAttributeMaxDynamicSharedMemorySize, FLASH_SMEM);

    dim3 gBlk(256);
    dim3 gGrid(DMODEL / GBN, MROWS / GBM);   // 8 x 64

    // Projections (head-split epilogue)
    gemm_nt_bias<<<gGrid, gBlk>>>(query, Wq, bq, qp, DMODEL, DMODEL, 1);
    gemm_nt_bias<<<gGrid, gBlk>>>(key,   Wk, bk, kp, DMODEL, DMODEL, 1);
    gemm_nt_bias<<<gGrid, gBlk>>>(value, Wv, bv, vp, DMODEL, DMODEL, 1);

    // Attention
    dim3 fGrid(SEQ / FBM, BHTOT);            // 32 x 64
    flash_attn_kernel<<<fGrid, 256, FLASH_SMEM>>>(qp, kp, vp, ctxp);

    // Output projection
    gemm_nt_bias<<<gGrid, gBlk>>>(ctxp, Wo, bo, out, DMODEL, DMODEL, 0);
}

// round 11
// speedup vs baseline: 1.1871x; 1.0600x over previous
#include <cuda_runtime.h>
#include <math.h>

// Problem constants (fixed by reference: B=4, S=2048, D_MODEL=1024, H=16, DK=64)
#define BATCH    4
#define SEQ      2048
#define DMODEL   1024
#define NHEADS   16
#define DK       64
#define BHTOT    (BATCH * NHEADS)
#define MROWS    (BATCH * SEQ)          // 8192

typedef unsigned long long u64;

// ---------------------------------------------------------------------------
// Packed fp32x2 helpers (Blackwell sm_100+ : SASS FFMA2 — 2x fp32 FMA/instr,
// bit-exact fp32 arithmetic; ptxas never auto-fuses, must come from PTX)
// ---------------------------------------------------------------------------
__device__ __forceinline__ u64 dup_f2(float x) {
    u64 r; asm("mov.b64 %0, {%1, %1};" : "=l"(r) : "f"(x)); return r;
}
__device__ __forceinline__ void fma_f2(u64& d, u64 a, u64 b) {
    asm("fma.rn.f32x2 %0, %1, %2, %0;" : "+l"(d) : "l"(a), "l"(b));
}
__device__ __forceinline__ void mul_f2(u64& d, u64 a, u64 b) {
    asm("mul.rn.f32x2 %0, %1, %2;" : "=l"(d) : "l"(a), "l"(b));
}
__device__ __forceinline__ float2 unp_f2(u64 v) {
    float lo, hi; asm("mov.b64 {%0, %1}, %2;" : "=f"(lo), "=f"(hi) : "l"(v));
    return make_float2(lo, hi);
}

// ---------------------------------------------------------------------------
// Scratch (static device globals — no runtime allocation)
// ---------------------------------------------------------------------------
__device__ float g_q[BHTOT * SEQ * DK];      // [b*H+h][s][d]
__device__ float g_k[BHTOT * SEQ * DK];
__device__ float g_v[BHTOT * SEQ * DK];
__device__ float g_ctx[MROWS * DMODEL];      // [b*S+s][h*DK+d]

// ---------------------------------------------------------------------------
// GEMM: C[m,n] = sum_k A[m,k] * W[n,k] + bias[n]   (NT, both K-contiguous)
// Tile 128x128x16, 256 threads, 8x8 micro-tile per thread. FFMA2 accumulators.
// (measured ~124 TF/s — at the FFMA2 ceiling; unchanged this round)
// ---------------------------------------------------------------------------
#define GBM 128
#define GBN 128
#define GBK 16
#define GSTR 132

__global__ __launch_bounds__(256) void gemm_nt_bias(
    const float* __restrict__ A, const float* __restrict__ W,
    const float* __restrict__ bias, float* __restrict__ C,
    int K, int N, int headsplit)
{
    __shared__ float As[GBK * GSTR];
    __shared__ float Bs[GBK * GSTR];

    const int tid = threadIdx.x;
    const int tx = tid & 15;
    const int ty = tid >> 4;
    const int mBase = blockIdx.y * GBM;
    const int nBase = blockIdx.x * GBN;

    const float* Aptr = A + (size_t)mBase * K;
    const float* Wptr = W + (size_t)nBase * K;

    u64 acc[8][4];
#pragma unroll
    for (int i = 0; i < 8; i++)
#pragma unroll
        for (int j = 0; j < 4; j++) acc[i][j] = 0ull;

    for (int k0 = 0; k0 < K; k0 += GBK) {
#pragma unroll
        for (int i = 0; i < 2; i++) {
            int v   = tid * 2 + i;
            int row = v >> 2;
            int kc  = (v & 3) * 4;
            float4 a = *(const float4*)(Aptr + (size_t)row * K + k0 + kc);
            float4 b = *(const float4*)(Wptr + (size_t)row * K + k0 + kc);
            As[(kc + 0) * GSTR + row] = a.x;
            As[(kc + 1) * GSTR + row] = a.y;
            As[(kc + 2) * GSTR + row] = a.z;
            As[(kc + 3) * GSTR + row] = a.w;
            Bs[(kc + 0) * GSTR + row] = b.x;
            Bs[(kc + 1) * GSTR + row] = b.y;
            Bs[(kc + 2) * GSTR + row] = b.z;
            Bs[(kc + 3) * GSTR + row] = b.w;
        }
        __syncthreads();

#pragma unroll
        for (int k = 0; k < GBK; k++) {
            float4 a0 = *(const float4*)&As[k * GSTR + ty * 8];
            float4 a1 = *(const float4*)&As[k * GSTR + ty * 8 + 4];
            ulonglong2 b0 = *(const ulonglong2*)&Bs[k * GSTR + tx * 8];
            ulonglong2 b1 = *(const ulonglong2*)&Bs[k * GSTR + tx * 8 + 4];
            u64 bb0 = b0.x, bb1 = b0.y, bb2 = b1.x, bb3 = b1.y;
            float av[8] = {a0.x, a0.y, a0.z, a0.w, a1.x, a1.y, a1.z, a1.w};
#pragma unroll
            for (int i = 0; i < 8; i++) {
                u64 ad = dup_f2(av[i]);
                fma_f2(acc[i][0], ad, bb0);
                fma_f2(acc[i][1], ad, bb1);
                fma_f2(acc[i][2], ad, bb2);
                fma_f2(acc[i][3], ad, bb3);
            }
        }
        __syncthreads();
    }

#pragma unroll
    for (int i = 0; i < 8; i++) {
        int m = mBase + ty * 8 + i;
#pragma unroll
        for (int jp = 0; jp < 4; jp++) {
            int n = nBase + tx * 8 + jp * 2;
            float2 v = unp_f2(acc[i][jp]);
            v.x += bias[n];
            v.y += bias[n + 1];
            if (!headsplit) {
                *(float2*)&C[(size_t)m * N + n] = v;
            } else {
                int b = m >> 11;
                int s = m & (SEQ - 1);
                int h = n >> 6;
                int d = n & (DK - 1);
                *(float2*)&C[(((size_t)(b * NHEADS + h)) * SEQ + s) * DK + d] = v;
            }
        }
    }
}

// ---------------------------------------------------------------------------
// Flash attention v2: 128-row Q tiles, 64-col KV tiles, online softmax.
// 256 threads as 16(tx) x 16(ty); micro-tile 8 rows x 4 cols per thread
// (LDS.128 per FFMA2 drops 0.25 -> 0.1875 vs v1).
// Softmax sum reduction DEFERRED: per-thread partial li, one lane-reduction
// at kernel end (halves SHFL traffic on the LSU pipe).
// smem: Qst [d][m] 64x128 (pre-scaled by 1/8), Kst [d][n] 64x68,
//       Vs [n][d] 64x64 (float4 fill), Ps [m][n] 128x64 (dedicated).
// 97KB smem -> 2 blocks/SM at <=128 regs.
// ---------------------------------------------------------------------------
#define FBM 128
#define FBN 64
#define KST 68
#define FLASH_SMEM ((DK * FBM + DK * KST + FBN * DK + FBM * FBN) * (int)sizeof(float))

extern __shared__ float fsm[];

__global__ __launch_bounds__(256, 2) void flash_attn_kernel(
    const float* __restrict__ Q, const float* __restrict__ K,
    const float* __restrict__ V, float* __restrict__ Octx)
{
    float* Qst = fsm;                       // [64][128]  Qst[d*128 + m]
    float* Kst = Qst + DK * FBM;            // [64][68]   Kst[d*68 + n]
    float* Vs  = Kst + DK * KST;            // [64][64]   Vs[n*64 + d]
    float* Ps  = Vs + FBN * DK;             // [128][64]  Ps[m*64 + n]

    const int tid = threadIdx.x;
    const int tx = tid & 15;
    const int ty = tid >> 4;
    const int bh = blockIdx.y;
    const int mBase = blockIdx.x * FBM;

    const float* Qp = Q + (size_t)bh * SEQ * DK + (size_t)mBase * DK;
    const float* Kp = K + (size_t)bh * SEQ * DK;
    const float* Vp = V + (size_t)bh * SEQ * DK;

    // Q tile: load float4, scatter transposed, fold 1/sqrt(DK)=0.125 (exact)
    for (int idx = tid; idx < FBM * 16; idx += 256) {
        int m = idx >> 4, c4 = (idx & 15) * 4;
        float4 q = *(const float4*)(Qp + (size_t)m * DK + c4);
        Qst[(c4 + 0) * FBM + m] = q.x * 0.125f;
        Qst[(c4 + 1) * FBM + m] = q.y * 0.125f;
        Qst[(c4 + 2) * FBM + m] = q.z * 0.125f;
        Qst[(c4 + 3) * FBM + m] = q.w * 0.125f;
    }

    u64 acc[8][2];                 // 8 rows x 2 col-pairs (packed f32x2)
    float mi[8], li[8];
#pragma unroll
    for (int i = 0; i < 8; i++) {
        mi[i] = -1e30f; li[i] = 0.0f;
        acc[i][0] = 0ull; acc[i][1] = 0ull;
    }

    for (int n0 = 0; n0 < SEQ; n0 += FBN) {
        __syncthreads();
        // K tile transposed (scalar scatter), V tile straight copy (float4)
        for (int idx = tid; idx < FBN * DK; idx += 256) {
            int n = idx >> 6, d = idx & 63;
            Kst[d * KST + n] = Kp[(size_t)(n0 + n) * DK + d];
        }
        for (int idx = tid; idx < (FBN * DK) / 4; idx += 256) {
            *(float4*)&Vs[idx * 4] = *(const float4*)(Vp + (size_t)n0 * DK + idx * 4);
        }
        __syncthreads();

        // S = Q K^T (scale pre-folded into Q)
        u64 sp[8][2];
#pragma unroll
        for (int i = 0; i < 8; i++) { sp[i][0] = 0ull; sp[i][1] = 0ull; }

#pragma unroll 4
        for (int d = 0; d < DK; d++) {
            ulonglong2 b2 = *(const ulonglong2*)&Kst[d * KST + tx * 4];
            float4 a0 = *(const float4*)&Qst[d * FBM + ty * 8];
            float4 a1 = *(const float4*)&Qst[d * FBM + ty * 8 + 4];
            float av[8] = {a0.x, a0.y, a0.z, a0.w, a1.x, a1.y, a1.z, a1.w};
#pragma unroll
            for (int i = 0; i < 8; i++) {
                u64 ad = dup_f2(av[i]);
                fma_f2(sp[i][0], ad, b2.x);
                fma_f2(sp[i][1], ad, b2.y);
            }
        }

        // Unpack S
        float s[8][4];
#pragma unroll
        for (int i = 0; i < 8; i++) {
            float2 p0 = unp_f2(sp[i][0]);
            float2 p1 = unp_f2(sp[i][1]);
            s[i][0] = p0.x; s[i][1] = p0.y; s[i][2] = p1.x; s[i][3] = p1.y;
        }

        // Online softmax: max reduced across 16 tx lanes; SUM kept per-thread
#pragma unroll
        for (int i = 0; i < 8; i++) {
            float rm = fmaxf(fmaxf(s[i][0], s[i][1]), fmaxf(s[i][2], s[i][3]));
#pragma unroll
            for (int off = 8; off > 0; off >>= 1)
                rm = fmaxf(rm, __shfl_xor_sync(0xffffffffu, rm, off));
            float mnew = fmaxf(mi[i], rm);
            float alpha = __expf(mi[i] - mnew);
            float rs = 0.0f;
#pragma unroll
            for (int j = 0; j < 4; j++) {
                s[i][j] = __expf(s[i][j] - mnew);
                rs += s[i][j];
            }
            li[i] = li[i] * alpha + rs;     // per-thread partial (4 cols)
            mi[i] = mnew;
            u64 al = dup_f2(alpha);
            mul_f2(acc[i][0], acc[i][0], al);
            mul_f2(acc[i][1], acc[i][1], al);
        }

        __syncthreads();
#pragma unroll
        for (int i = 0; i < 8; i++)
            *(float4*)&Ps[(ty * 8 + i) * FBN + tx * 4] =
                make_float4(s[i][0], s[i][1], s[i][2], s[i][3]);
        __syncthreads();

        // O += P @ V — n in chunks of 4; P rows as LDS.128 broadcast
#pragma unroll 2
        for (int n = 0; n < FBN; n += 4) {
            float4 p4[8];
#pragma unroll
            for (int i = 0; i < 8; i++)
                p4[i] = *(const float4*)&Ps[(ty * 8 + i) * FBN + n];
#pragma unroll
            for (int nn = 0; nn < 4; nn++) {
                ulonglong2 v2 = *(const ulonglong2*)&Vs[(n + nn) * DK + tx * 4];
#pragma unroll
                for (int i = 0; i < 8; i++) {
                    u64 pd = dup_f2(((const float*)&p4[i])[nn]);
                    fma_f2(acc[i][0], pd, v2.x);
                    fma_f2(acc[i][1], pd, v2.y);
                }
            }
        }
    }

    // Deferred sum reduction (once per kernel), normalize, write back
    const int b = bh >> 4;
    const int h = bh & 15;
#pragma unroll
    for (int i = 0; i < 8; i++) {
        float lsum = li[i];
#pragma unroll
        for (int off = 8; off > 0; off >>= 1)
            lsum += __shfl_xor_sync(0xffffffffu, lsum, off);
        float inv = 1.0f / lsum;
        int srow = mBase + ty * 8 + i;
        float2 o0 = unp_f2(acc[i][0]);
        float2 o1 = unp_f2(acc[i][1]);
        float* dst = Octx + ((size_t)(b * SEQ + srow)) * DMODEL + h * DK + tx * 4;
        *(float4*)dst = make_float4(o0.x * inv, o0.y * inv, o1.x * inv, o1.y * inv);
    }
}

// ---------------------------------------------------------------------------
// Launch
// ---------------------------------------------------------------------------
extern "C" void kernel_launch(void* const* d_in, const int* in_sizes, int n_in,
                              void* d_out, int out_size)
{
    const float* query = (const float*)d_in[0];
    const float* key   = (const float*)d_in[1];
    const float* value = (const float*)d_in[2];
    const float* Wq    = (const float*)d_in[3];
    const float* bq    = (const float*)d_in[4];
    const float* Wk    = (const float*)d_in[5];
    const float* bk    = (const float*)d_in[6];
    const float* Wv    = (const float*)d_in[7];
    const float* bv    = (const float*)d_in[8];
    const float* Wo    = (const float*)d_in[9];
    const float* bo    = (const float*)d_in[10];
    float* out = (float*)d_out;

    float *qp, *kp, *vp, *ctxp;
    cudaGetSymbolAddress((void**)&qp,   g_q);
    cudaGetSymbolAddress((void**)&kp,   g_k);
    cudaGetSymbolAddress((void**)&vp,   g_v);
    cudaGetSymbolAddress((void**)&ctxp, g_ctx);

    cudaFuncSetAttribute(flash_attn_kernel,
                         cudaFuncAttributeMaxDynamicSharedMemorySize, FLASH_SMEM);

    dim3 gBlk(256);
    dim3 gGrid(DMODEL / GBN, MROWS / GBM);   // 8 x 64

    // Projections (head-split epilogue)
    gemm_nt_bias<<<gGrid, gBlk>>>(query, Wq, bq, qp, DMODEL, DMODEL, 1);
    gemm_nt_bias<<<gGrid, gBlk>>>(key,   Wk, bk, kp, DMODEL, DMODEL, 1);
    gemm_nt_bias<<<gGrid, gBlk>>>(value, Wv, bv, vp, DMODEL, DMODEL, 1);

    // Attention
    dim3 fGrid(SEQ / FBM, BHTOT);            // 16 x 64
    flash_attn_kernel<<<fGrid, 256, FLASH_SMEM>>>(qp, kp, vp, ctxp);

    // Output projection
    gemm_nt_bias<<<gGrid, gBlk>>>(ctxp, Wo, bo, out, DMODEL, DMODEL, 0);
}

// round 12
// speedup vs baseline: 1.2524x; 1.0550x over previous
#include <cuda_runtime.h>
#include <math.h>

// Problem constants (fixed by reference: B=4, S=2048, D_MODEL=1024, H=16, DK=64)
#define BATCH    4
#define SEQ      2048
#define DMODEL   1024
#define NHEADS   16
#define DK       64
#define BHTOT    (BATCH * NHEADS)
#define MROWS    (BATCH * SEQ)          // 8192

typedef unsigned long long u64;
typedef unsigned int u32;

// ---------------------------------------------------------------------------
// Packed fp32x2 helpers (Blackwell: SASS FFMA2 — 2x fp32 FMA/instr, bit-exact)
// ---------------------------------------------------------------------------
__device__ __forceinline__ u64 dup_f2(float x) {
    u64 r; asm("mov.b64 %0, {%1, %1};" : "=l"(r) : "f"(x)); return r;
}
__device__ __forceinline__ void fma_f2(u64& d, u64 a, u64 b) {
    asm("fma.rn.f32x2 %0, %1, %2, %0;" : "+l"(d) : "l"(a), "l"(b));
}
__device__ __forceinline__ void mul_f2(u64& d, u64 a, u64 b) {
    asm("mul.rn.f32x2 %0, %1, %2;" : "=l"(d) : "l"(a), "l"(b));
}
__device__ __forceinline__ float2 unp_f2(u64 v) {
    float lo, hi; asm("mov.b64 {%0, %1}, %2;" : "=f"(lo), "=f"(hi) : "l"(v));
    return make_float2(lo, hi);
}

// cp.async helpers (16B, L1-bypass)
__device__ __forceinline__ void cp16(u32 dst, const void* src) {
    asm volatile("cp.async.cg.shared.global [%0], [%1], 16;" :: "r"(dst), "l"(src));
}
__device__ __forceinline__ void cp_commit() {
    asm volatile("cp.async.commit_group;");
}
__device__ __forceinline__ void cp_wait_all() {
    asm volatile("cp.async.wait_group 0;");
}

// ---------------------------------------------------------------------------
// Scratch (static device globals — no runtime allocation)
// ---------------------------------------------------------------------------
__device__ float g_q[BHTOT * DK * SEQ];      // [bh][d][s]  (TRANSPOSED, pre-scaled)
__device__ float g_k[BHTOT * DK * SEQ];      // [bh][d][s]  (TRANSPOSED)
__device__ float g_v[BHTOT * SEQ * DK];      // [bh][s][d]
__device__ float g_ctx[MROWS * DMODEL];      // [b*S+s][h*DK+d]

// ---------------------------------------------------------------------------
// GEMM: C[m,n] = (sum_k A[m,k] * W[n,k] + bias[n]) * oscale
// mode 0: C[m][n] row-major     mode 1: [bh][s][d]     mode 2: [bh][d][s] (T)
// Tile 128x128x16, 256 threads, 8x8 micro-tile, FFMA2 accumulators.
// ---------------------------------------------------------------------------
#define GBM 128
#define GBN 128
#define GBK 16
#define GSTR 132

__global__ __launch_bounds__(256) void gemm_nt_bias(
    const float* __restrict__ A, const float* __restrict__ W,
    const float* __restrict__ bias, float* __restrict__ C,
    int K, int N, int mode, float oscale)
{
    __shared__ float As[GBK * GSTR];
    __shared__ float Bs[GBK * GSTR];

    const int tid = threadIdx.x;
    const int tx = tid & 15;
    const int ty = tid >> 4;
    const int mBase = blockIdx.y * GBM;
    const int nBase = blockIdx.x * GBN;

    const float* Aptr = A + (size_t)mBase * K;
    const float* Wptr = W + (size_t)nBase * K;

    u64 acc[8][4];
#pragma unroll
    for (int i = 0; i < 8; i++)
#pragma unroll
        for (int j = 0; j < 4; j++) acc[i][j] = 0ull;

    for (int k0 = 0; k0 < K; k0 += GBK) {
#pragma unroll
        for (int i = 0; i < 2; i++) {
            int v   = tid * 2 + i;
            int row = v >> 2;
            int kc  = (v & 3) * 4;
            float4 a = *(const float4*)(Aptr + (size_t)row * K + k0 + kc);
            float4 b = *(const float4*)(Wptr + (size_t)row * K + k0 + kc);
            As[(kc + 0) * GSTR + row] = a.x;
            As[(kc + 1) * GSTR + row] = a.y;
            As[(kc + 2) * GSTR + row] = a.z;
            As[(kc + 3) * GSTR + row] = a.w;
            Bs[(kc + 0) * GSTR + row] = b.x;
            Bs[(kc + 1) * GSTR + row] = b.y;
            Bs[(kc + 2) * GSTR + row] = b.z;
            Bs[(kc + 3) * GSTR + row] = b.w;
        }
        __syncthreads();

#pragma unroll
        for (int k = 0; k < GBK; k++) {
            float4 a0 = *(const float4*)&As[k * GSTR + ty * 8];
            float4 a1 = *(const float4*)&As[k * GSTR + ty * 8 + 4];
            ulonglong2 b0 = *(const ulonglong2*)&Bs[k * GSTR + tx * 8];
            ulonglong2 b1 = *(const ulonglong2*)&Bs[k * GSTR + tx * 8 + 4];
            u64 bb0 = b0.x, bb1 = b0.y, bb2 = b1.x, bb3 = b1.y;
            float av[8] = {a0.x, a0.y, a0.z, a0.w, a1.x, a1.y, a1.z, a1.w};
#pragma unroll
            for (int i = 0; i < 8; i++) {
                u64 ad = dup_f2(av[i]);
                fma_f2(acc[i][0], ad, bb0);
                fma_f2(acc[i][1], ad, bb1);
                fma_f2(acc[i][2], ad, bb2);
                fma_f2(acc[i][3], ad, bb3);
            }
        }
        __syncthreads();
    }

#pragma unroll
    for (int i = 0; i < 8; i++) {
        int m = mBase + ty * 8 + i;
        int b = m >> 11;              // m / SEQ
        int s = m & (SEQ - 1);
#pragma unroll
        for (int jp = 0; jp < 4; jp++) {
            int n = nBase + tx * 8 + jp * 2;
            float2 v = unp_f2(acc[i][jp]);
            v.x = (v.x + bias[n])     * oscale;
            v.y = (v.y + bias[n + 1]) * oscale;
            if (mode == 0) {
                *(float2*)&C[(size_t)m * N + n] = v;
            } else if (mode == 1) {
                int h = n >> 6, d = n & (DK - 1);
                *(float2*)&C[(((size_t)(b * NHEADS + h)) * SEQ + s) * DK + d] = v;
            } else {
                int h = n >> 6, d = n & (DK - 1);
                size_t base = (((size_t)(b * NHEADS + h)) * DK + d) * SEQ + s;
                C[base]       = v.x;
                C[base + SEQ] = v.y;   // d+1, same head (pairs stay inside a head)
            }
        }
    }
}

// ---------------------------------------------------------------------------
// Flash attention v3: 128-row Q tiles, 64-col KV tiles, online softmax.
// Q and K arrive TRANSPOSED ([bh][d][s], Q pre-scaled) -> every smem fill is a
// straight contiguous cp.async copy. V double-buffered; K prefetched into its
// single buffer right after its last read, overlapping P-store + P@V.
// 256 threads as 16(tx) x 16(ty); 8x4 micro-tile, FFMA2, deferred li reduce.
// smem: Qst[64][128] 32KB, Kst[64][64] 16KB, Vs 2x[64][64] 32KB, Ps[128][64]
// 32KB = 112KB -> 2 CTAs/SM.
// ---------------------------------------------------------------------------
#define FBM 128
#define FBN 64
#define NTILE (SEQ / FBN)
#define FLASH_SMEM ((DK * FBM + DK * FBN + 2 * FBN * DK + FBM * FBN) * (int)sizeof(float))

extern __shared__ float fsm[];

__global__ __launch_bounds__(256, 2) void flash_attn_kernel(
    const float* __restrict__ Q, const float* __restrict__ K,
    const float* __restrict__ V, float* __restrict__ Octx)
{
    float* Qst = fsm;                       // [64][128]  Qst[d*128 + m]
    float* Kst = Qst + DK * FBM;            // [64][64]   Kst[d*64 + n]
    float* Vs0 = Kst + DK * FBN;            // [64][64]   ping
    float* Vs1 = Vs0 + FBN * DK;            // [64][64]   pong
    float* Ps  = Vs1 + FBN * DK;            // [128][64]  Ps[m*64 + n]

    const int tid = threadIdx.x;
    const int tx = tid & 15;
    const int ty = tid >> 4;
    const int bh = blockIdx.y;
    const int mBase = blockIdx.x * FBM;

    const float* Qt = Q + (size_t)bh * DK * SEQ;   // [d][s]
    const float* Kt = K + (size_t)bh * DK * SEQ;   // [d][s]
    const float* Vp = V + (size_t)bh * SEQ * DK;   // [s][d]

    const u32 sQ  = (u32)__cvta_generic_to_shared(Qst);
    const u32 sK  = (u32)__cvta_generic_to_shared(Kst);
    const u32 sV0 = (u32)__cvta_generic_to_shared(Vs0);
    const u32 sV1 = (u32)__cvta_generic_to_shared(Vs1);

    // Preload Q (straight copy rows of Qt), K tile 0, V tile 0 — all async.
#pragma unroll
    for (int k = 0; k < 8; k++) {              // 2048 16B chunks
        int c = tid + k * 256;
        int d = c >> 5, m4 = (c & 31) * 4;
        cp16(sQ + (u32)(d * FBM + m4) * 4, Qt + (size_t)d * SEQ + mBase + m4);
    }
#pragma unroll
    for (int k = 0; k < 4; k++) {              // 1024 16B chunks
        int c = tid + k * 256;
        int d = c >> 4, n4 = (c & 15) * 4;
        cp16(sK + (u32)(d * FBN + n4) * 4, Kt + (size_t)d * SEQ + n4);
    }
#pragma unroll
    for (int k = 0; k < 4; k++) {              // 1024 16B chunks
        int c = tid + k * 256;
        cp16(sV0 + (u32)c * 16, Vp + c * 4);
    }
    cp_commit();
    cp_wait_all();
    __syncthreads();

    u64 acc[8][2];
    float mi[8], li[8];
#pragma unroll
    for (int i = 0; i < 8; i++) {
        mi[i] = -1e30f; li[i] = 0.0f;
        acc[i][0] = 0ull; acc[i][1] = 0ull;
    }

    for (int it = 0; it < NTILE; it++) {
        const int n0 = it * FBN;
        const float* Vcur = (it & 1) ? Vs1 : Vs0;
        const u32 sVnxt   = (it & 1) ? sV0 : sV1;

        // Prefetch next V tile (overlaps the whole tile's compute)
        if (it + 1 < NTILE) {
#pragma unroll
            for (int k = 0; k < 4; k++) {
                int c = tid + k * 256;
                cp16(sVnxt + (u32)c * 16, Vp + (size_t)(n0 + FBN) * DK + c * 4);
            }
            cp_commit();
        }

        // S = Q K^T (scale pre-folded into Q at projection time)
        u64 sp[8][2];
#pragma unroll
        for (int i = 0; i < 8; i++) { sp[i][0] = 0ull; sp[i][1] = 0ull; }

#pragma unroll 4
        for (int d = 0; d < DK; d++) {
            ulonglong2 b2 = *(const ulonglong2*)&Kst[d * FBN + tx * 4];
            float4 a0 = *(const float4*)&Qst[d * FBM + ty * 8];
            float4 a1 = *(const float4*)&Qst[d * FBM + ty * 8 + 4];
            float av[8] = {a0.x, a0.y, a0.z, a0.w, a1.x, a1.y, a1.z, a1.w};
#pragma unroll
            for (int i = 0; i < 8; i++) {
                u64 ad = dup_f2(av[i]);
                fma_f2(sp[i][0], ad, b2.x);
                fma_f2(sp[i][1], ad, b2.y);
            }
        }

        float s[8][4];
#pragma unroll
        for (int i = 0; i < 8; i++) {
            float2 p0 = unp_f2(sp[i][0]);
            float2 p1 = unp_f2(sp[i][1]);
            s[i][0] = p0.x; s[i][1] = p0.y; s[i][2] = p1.x; s[i][3] = p1.y;
        }

        // Online softmax: max across 16 tx lanes; sum kept per-thread
#pragma unroll
        for (int i = 0; i < 8; i++) {
            float rm = fmaxf(fmaxf(s[i][0], s[i][1]), fmaxf(s[i][2], s[i][3]));
#pragma unroll
            for (int off = 8; off > 0; off >>= 1)
                rm = fmaxf(rm, __shfl_xor_sync(0xffffffffu, rm, off));
            float mnew = fmaxf(mi[i], rm);
            float alpha = __expf(mi[i] - mnew);
            float rs = 0.0f;
#pragma unroll
            for (int j = 0; j < 4; j++) {
                s[i][j] = __expf(s[i][j] - mnew);
                rs += s[i][j];
            }
            li[i] = li[i] * alpha + rs;
            mi[i] = mnew;
            u64 al = dup_f2(alpha);
            mul_f2(acc[i][0], acc[i][0], al);
            mul_f2(acc[i][1], acc[i][1], al);
        }

        __syncthreads();   // all warps done reading Kst (S-loop complete)

        // Prefetch next K tile into Kst — overlaps P store + P@V below
        if (it + 1 < NTILE) {
#pragma unroll
            for (int k = 0; k < 4; k++) {
                int c = tid + k * 256;
                int d = c >> 4, n4 = (c & 15) * 4;
                cp16(sK + (u32)(d * FBN + n4) * 4,
                     Kt + (size_t)d * SEQ + (n0 + FBN) + n4);
            }
            cp_commit();
        }

#pragma unroll
        for (int i = 0; i < 8; i++)
            *(float4*)&Ps[(ty * 8 + i) * FBN + tx * 4] =
                make_float4(s[i][0], s[i][1], s[i][2], s[i][3]);
        __syncthreads();

        // O += P @ V — n in chunks of 4; P rows as LDS.128 broadcast
#pragma unroll 2
        for (int n = 0; n < FBN; n += 4) {
            float4 p4[8];
#pragma unroll
            for (int i = 0; i < 8; i++)
                p4[i] = *(const float4*)&Ps[(ty * 8 + i) * FBN + n];
#pragma unroll
            for (int nn = 0; nn < 4; nn++) {
                ulonglong2 v2 = *(const ulonglong2*)&Vcur[(n + nn) * DK + tx * 4];
#pragma unroll
                for (int i = 0; i < 8; i++) {
                    u64 pd = dup_f2(((const float*)&p4[i])[nn]);
                    fma_f2(acc[i][0], pd, v2.x);
                    fma_f2(acc[i][1], pd, v2.y);
                }
            }
        }

        cp_wait_all();     // next K and V landed
        __syncthreads();
    }

    // Deferred sum reduction, normalize, write merged-head layout
    const int b = bh >> 4;
    const int h = bh & 15;
#pragma unroll
    for (int i = 0; i < 8; i++) {
        float lsum = li[i];
#pragma unroll
        for (int off = 8; off > 0; off >>= 1)
            lsum += __shfl_xor_sync(0xffffffffu, lsum, off);
        float inv = 1.0f / lsum;
        int srow = mBase + ty * 8 + i;
        float2 o0 = unp_f2(acc[i][0]);
        float2 o1 = unp_f2(acc[i][1]);
        float* dst = Octx + ((size_t)(b * SEQ + srow)) * DMODEL + h * DK + tx * 4;
        *(float4*)dst = make_float4(o0.x * inv, o0.y * inv, o1.x * inv, o1.y * inv);
    }
}

// ---------------------------------------------------------------------------
// Launch
// ---------------------------------------------------------------------------
extern "C" void kernel_launch(void* const* d_in, const int* in_sizes, int n_in,
                              void* d_out, int out_size)
{
    const float* query = (const float*)d_in[0];
    const float* key   = (const float*)d_in[1];
    const float* value = (const float*)d_in[2];
    const float* Wq    = (const float*)d_in[3];
    const float* bq    = (const float*)d_in[4];
    const float* Wk    = (const float*)d_in[5];
    const float* bk    = (const float*)d_in[6];
    const float* Wv    = (const float*)d_in[7];
    const float* bv    = (const float*)d_in[8];
    const float* Wo    = (const float*)d_in[9];
    const float* bo    = (const float*)d_in[10];
    float* out = (float*)d_out;

    float *qp, *kp, *vp, *ctxp;
    cudaGetSymbolAddress((void**)&qp,   g_q);
    cudaGetSymbolAddress((void**)&kp,   g_k);
    cudaGetSymbolAddress((void**)&vp,   g_v);
    cudaGetSymbolAddress((void**)&ctxp, g_ctx);

    cudaFuncSetAttribute(flash_attn_kernel,
                         cudaFuncAttributeMaxDynamicSharedMemorySize, FLASH_SMEM);

    dim3 gBlk(256);
    dim3 gGrid(DMODEL / GBN, MROWS / GBM);   // 8 x 64

    // Projections: Q transposed + pre-scaled by 1/sqrt(DK)=0.125 (exact),
    // K transposed, V head-split.
    gemm_nt_bias<<<gGrid, gBlk>>>(query, Wq, bq, qp, DMODEL, DMODEL, 2, 0.125f);
    gemm_nt_bias<<<gGrid, gBlk>>>(key,   Wk, bk, kp, DMODEL, DMODEL, 2, 1.0f);
    gemm_nt_bias<<<gGrid, gBlk>>>(value, Wv, bv, vp, DMODEL, DMODEL, 1, 1.0f);

    // Attention
    dim3 fGrid(SEQ / FBM, BHTOT);            // 16 x 64
    flash_attn_kernel<<<fGrid, 256, FLASH_SMEM>>>(qp, kp, vp, ctxp);

    // Output projection
    gemm_nt_bias<<<gGrid, gBlk>>>(ctxp, Wo, bo, out, DMODEL, DMODEL, 0, 1.0f);
}